// round 1
// baseline (speedup 1.0000x reference)
#include <cuda_runtime.h>
#include <math.h>

// Problem constants (fixed shapes for this problem id)
#define N_EMB   8192
#define D       512
#define P_MAX   4096
#define NEG_MAX 16384
#define INV_T   (1.0f / 0.07f)

// LSE GEMM tiling
#define NSPLIT  8      // N-dimension splits (partial LSE per split)
#define BM      128    // anchors per block
#define BN      128    // columns per tile
#define NCHUNKS 8      // tiles per split: NSPLIT*NCHUNKS*BN == N_EMB
#define BK      16

// Scratch (device globals: no allocation allowed)
__device__ float g_e[N_EMB * D];            // normalized embeddings (16 MB)
__device__ float g_pm[P_MAX * NSPLIT];      // partial max
__device__ float g_ps[P_MAX * NSPLIT];      // partial sum-exp
__device__ float g_posdot[P_MAX];
__device__ float g_negdot[NEG_MAX];

// ---------------------------------------------------------------------------
// 1) Row-normalize embeddings: e = emb / max(||emb||, 1e-8)
// One block per row, 128 threads, each handles one float4 (D/4 = 128).
__global__ void k_normalize(const float* __restrict__ emb) {
    int row = blockIdx.x;
    int t = threadIdx.x;
    const float4* src = (const float4*)emb + row * (D / 4);
    float4 v = src[t];
    float ss = v.x * v.x + v.y * v.y + v.z * v.z + v.w * v.w;
#pragma unroll
    for (int o = 16; o; o >>= 1) ss += __shfl_xor_sync(0xffffffffu, ss, o);
    __shared__ float red[4];
    if ((t & 31) == 0) red[t >> 5] = ss;
    __syncthreads();
    float tot = red[0] + red[1] + red[2] + red[3];
    float inv = 1.0f / fmaxf(sqrtf(tot), 1e-8f);
    v.x *= inv; v.y *= inv; v.z *= inv; v.w *= inv;
    ((float4*)g_e)[row * (D / 4) + t] = v;
}

// ---------------------------------------------------------------------------
// 2) Pair dot products (cosine sims of normalized rows). One warp per pair.
__global__ void k_pairdot(const int* __restrict__ pa, const int* __restrict__ pt,
                          const int* __restrict__ na, const int* __restrict__ nt,
                          int nPos, int nNeg) {
    int warp = (blockIdx.x * blockDim.x + threadIdx.x) >> 5;
    int lane = threadIdx.x & 31;
    if (warp >= nPos + nNeg) return;
    int a, b;
    float* out;
    if (warp < nPos) { a = pa[warp]; b = pt[warp]; out = &g_posdot[warp]; }
    else             { int w = warp - nPos; a = na[w]; b = nt[w]; out = &g_negdot[w]; }
    const float4* va = (const float4*)(g_e + (size_t)a * D);
    const float4* vb = (const float4*)(g_e + (size_t)b * D);
    float s = 0.0f;
#pragma unroll 4
    for (int i = lane; i < D / 4; i += 32) {
        float4 x = va[i], y = vb[i];
        s += x.x * y.x + x.y * y.y + x.z * y.z + x.w * y.w;
    }
#pragma unroll
    for (int o = 16; o; o >>= 1) s += __shfl_xor_sync(0xffffffffu, s, o);
    if (lane == 0) *out = s;
}

// ---------------------------------------------------------------------------
// 3) Fused gathered-GEMM + online logsumexp partials.
// Block (mtile, nsplit): 128 anchors x 1024 columns. 256 threads, 8x8 microtile.
__global__ __launch_bounds__(256) void k_lse(const int* __restrict__ pa, int nPos) {
    int m0 = blockIdx.x * BM;
    int nsplit = blockIdx.y;
    int tid = threadIdx.x;
    int tx = tid & 15;       // N direction (16 lanes)
    int ty = tid >> 4;       // M direction (16 groups)

    __shared__ float As[BK][BM];
    __shared__ float Bs[BK][BN];
    __shared__ int arow[BM];

    if (tid < BM) {
        int p = m0 + tid;
        arow[tid] = (p < nPos) ? pa[p] : 0;
    }
    __syncthreads();

    float rm[8], rs[8];
#pragma unroll
    for (int i = 0; i < 8; i++) { rm[i] = -INFINITY; rs[i] = 0.0f; }

    for (int nc = 0; nc < NCHUNKS; nc++) {
        int n0 = nsplit * (BN * NCHUNKS) + nc * BN;

        float acc[8][8];
#pragma unroll
        for (int i = 0; i < 8; i++)
#pragma unroll
            for (int j = 0; j < 8; j++) acc[i][j] = 0.0f;

        for (int k0 = 0; k0 < D; k0 += BK) {
            // Load A (gathered) and B tiles: 2048 floats each = 2 rounds of 256 float4s
#pragma unroll
            for (int r = 0; r < 2; r++) {
                int e  = r * 256 + tid;      // float4 index in [0,512)
                int m  = e >> 2;             // row within tile
                int kk = (e & 3) * 4;        // k offset within BK
                float4 va = *(const float4*)(g_e + (size_t)arow[m] * D + k0 + kk);
                As[kk + 0][m] = va.x; As[kk + 1][m] = va.y;
                As[kk + 2][m] = va.z; As[kk + 3][m] = va.w;
                float4 vb = *(const float4*)(g_e + (size_t)(n0 + m) * D + k0 + kk);
                Bs[kk + 0][m] = vb.x; Bs[kk + 1][m] = vb.y;
                Bs[kk + 2][m] = vb.z; Bs[kk + 3][m] = vb.w;
            }
            __syncthreads();

#pragma unroll
            for (int kk = 0; kk < BK; kk++) {
                float af[8], bf[8];
                *(float4*)&af[0] = *(const float4*)&As[kk][ty * 8];
                *(float4*)&af[4] = *(const float4*)&As[kk][ty * 8 + 4];
                *(float4*)&bf[0] = *(const float4*)&Bs[kk][tx * 8];
                *(float4*)&bf[4] = *(const float4*)&Bs[kk][tx * 8 + 4];
#pragma unroll
                for (int i = 0; i < 8; i++)
#pragma unroll
                    for (int j = 0; j < 8; j++) acc[i][j] += af[i] * bf[j];
            }
            __syncthreads();
        }

        // Online LSE update for this 128x128 tile (scaled domain: acc * INV_T)
#pragma unroll
        for (int i = 0; i < 8; i++) {
            float ml = acc[i][0];
#pragma unroll
            for (int j = 1; j < 8; j++) ml = fmaxf(ml, acc[i][j]);
            ml *= INV_T;
            float sl = 0.0f;
#pragma unroll
            for (int j = 0; j < 8; j++) sl += __expf(acc[i][j] * INV_T - ml);
            // combine across the 16 tx lanes (xor stays within low 4 bits of lane id)
#pragma unroll
            for (int o = 1; o < 16; o <<= 1) {
                float mo = __shfl_xor_sync(0xffffffffu, ml, o);
                float so = __shfl_xor_sync(0xffffffffu, sl, o);
                float nm = fmaxf(ml, mo);
                sl = sl * __expf(ml - nm) + so * __expf(mo - nm);
                ml = nm;
            }
            float nm = fmaxf(rm[i], ml);
            rs[i] = rs[i] * __expf(rm[i] - nm) + sl * __expf(ml - nm);
            rm[i] = nm;
        }
    }

    if (tx == 0) {
#pragma unroll
        for (int i = 0; i < 8; i++) {
            int row = m0 + ty * 8 + i;
            if (row < nPos) {
                g_pm[row * NSPLIT + nsplit] = rm[i];
                g_ps[row * NSPLIT + nsplit] = rs[i];
            }
        }
    }
}

// ---------------------------------------------------------------------------
// 4) Deterministic finalize: combine LSE partials, means, write 3 outputs.
__global__ void k_finalize(float* __restrict__ out, int nPos, int nNeg, int out_size) {
    int t = threadIdx.x;
    float lsum = 0.0f, psum = 0.0f, nsum = 0.0f;
    for (int p = t; p < nPos; p += 256) {
        float m = -INFINITY, s = 0.0f;
#pragma unroll
        for (int k = 0; k < NSPLIT; k++) {
            float mk = g_pm[p * NSPLIT + k], sk = g_ps[p * NSPLIT + k];
            float nm = fmaxf(m, mk);
            s = s * __expf(m - nm) + sk * __expf(mk - nm);
            m = nm;
        }
        float lse = m + logf(s);
        float d = g_posdot[p];
        lsum += lse - d * INV_T;
        psum += d;
    }
    for (int p = t; p < nNeg; p += 256) nsum += g_negdot[p];

    __shared__ float rl[256], rp[256], rn[256];
    rl[t] = lsum; rp[t] = psum; rn[t] = nsum;
    __syncthreads();
    for (int o = 128; o; o >>= 1) {
        if (t < o) { rl[t] += rl[t + o]; rp[t] += rp[t + o]; rn[t] += rn[t + o]; }
        __syncthreads();
    }
    if (t == 0) {
        if (out_size > 0) out[0] = rl[0] / (float)nPos;
        if (out_size > 1) out[1] = rp[0] / (float)nPos;
        if (out_size > 2) out[2] = rn[0] / (float)nNeg;
    }
}

// ---------------------------------------------------------------------------
extern "C" void kernel_launch(void* const* d_in, const int* in_sizes, int n_in,
                              void* d_out, int out_size) {
    const float* emb = (const float*)d_in[0];
    const int* pa = (const int*)d_in[1];
    const int* pt = (const int*)d_in[2];
    const int* na = (const int*)d_in[3];
    const int* nt = (const int*)d_in[4];
    int nPos = in_sizes[1];
    int nNeg = in_sizes[3];

    k_normalize<<<N_EMB, 128>>>(emb);

    int pairs = nPos + nNeg;
    int pblocks = (pairs * 32 + 255) / 256;
    k_pairdot<<<pblocks, 256>>>(pa, pt, na, nt, nPos, nNeg);

    dim3 grid((nPos + BM - 1) / BM, NSPLIT);
    k_lse<<<grid, 256>>>(pa, nPos);

    k_finalize<<<1, 256>>>((float*)d_out, nPos, nNeg, out_size);
}

// round 3
// speedup vs baseline: 3.7038x; 3.7038x over previous
#include <cuda_runtime.h>
#include <cuda_bf16.h>
#include <math.h>
#include <stdint.h>

// Problem constants (fixed shapes for this problem id)
#define N_EMB   8192
#define D       512
#define P_MAX   4096
#define NEG_MAX 16384
#define INV_T   (1.0f / 0.07f)

// MMA LSE GEMM tiling
#define BM 128
#define BN 128
#define BK 64
#define NSPLIT 16
#define NCHUNK 4
#define NPART  32

// Scratch (device globals: allocation is forbidden)
__device__ float         g_e [N_EMB * D];
__device__ __nv_bfloat16 g_eb[N_EMB * D];
__device__ float g_pm[P_MAX * NPART];
__device__ float g_ps[P_MAX * NPART];
__device__ float g_posdot [P_MAX];
__device__ float g_negdot [NEG_MAX];
__device__ float g_rowloss[P_MAX];

// ---------------------------------------------------------------------------
__global__ void k_normalize(const float* __restrict__ emb) {
    int row = blockIdx.x;
    int t = threadIdx.x;
    const float4* src = (const float4*)emb + row * (D / 4);
    float4 v = src[t];
    float ss = v.x * v.x + v.y * v.y + v.z * v.z + v.w * v.w;
#pragma unroll
    for (int o = 16; o; o >>= 1) ss += __shfl_xor_sync(0xffffffffu, ss, o);
    __shared__ float red[4];
    if ((t & 31) == 0) red[t >> 5] = ss;
    __syncthreads();
    float tot = red[0] + red[1] + red[2] + red[3];
    float inv = 1.0f / fmaxf(sqrtf(tot), 1e-8f);
    v.x *= inv; v.y *= inv; v.z *= inv; v.w *= inv;
    ((float4*)g_e)[row * (D / 4) + t] = v;
    __nv_bfloat162 b0 = __floats2bfloat162_rn(v.x, v.y);
    __nv_bfloat162 b1 = __floats2bfloat162_rn(v.z, v.w);
    ((__nv_bfloat162*)g_eb)[row * (D / 2) + t * 2 + 0] = b0;
    ((__nv_bfloat162*)g_eb)[row * (D / 2) + t * 2 + 1] = b1;
}

// ---------------------------------------------------------------------------
__global__ void k_pairdot(const int* __restrict__ pa, const int* __restrict__ pt,
                          const int* __restrict__ na, const int* __restrict__ nt,
                          int nPos, int nNeg) {
    int warp = (blockIdx.x * blockDim.x + threadIdx.x) >> 5;
    int lane = threadIdx.x & 31;
    if (warp >= nPos + nNeg) return;
    int a, b;
    float* outp;
    if (warp < nPos) {
        a = pa[warp]; b = pt[warp]; outp = &g_posdot[warp];
    } else {
        int w = warp - nPos;
        a = na[w]; b = nt[w]; outp = &g_negdot[w];
    }
    const float4* va = (const float4*)(g_e + (size_t)a * D);
    const float4* vb = (const float4*)(g_e + (size_t)b * D);
    float s = 0.0f;
#pragma unroll 4
    for (int i = lane; i < D / 4; i += 32) {
        float4 x = va[i];
        float4 y = vb[i];
        s += x.x * y.x + x.y * y.y + x.z * y.z + x.w * y.w;
    }
#pragma unroll
    for (int o = 16; o; o >>= 1) s += __shfl_xor_sync(0xffffffffu, s, o);
    if (lane == 0) *outp = s;
}

// ---------------------------------------------------------------------------
__device__ __forceinline__ void ldmatrix_x4(uint32_t* d, uint32_t addr) {
    asm volatile("ldmatrix.sync.aligned.m8n8.x4.shared.b16 {%0,%1,%2,%3}, [%4];"
                 : "=r"(d[0]), "=r"(d[1]), "=r"(d[2]), "=r"(d[3]) : "r"(addr));
}
__device__ __forceinline__ void mma16816(float* c, const uint32_t* a,
                                         uint32_t b0, uint32_t b1) {
    asm volatile("mma.sync.aligned.m16n8k16.row.col.f32.bf16.bf16.f32 "
                 "{%0,%1,%2,%3}, {%4,%5,%6,%7}, {%8,%9}, {%0,%1,%2,%3};"
                 : "+f"(c[0]), "+f"(c[1]), "+f"(c[2]), "+f"(c[3])
                 : "r"(a[0]), "r"(a[1]), "r"(a[2]), "r"(a[3]), "r"(b0), "r"(b1));
}
__device__ __forceinline__ uint32_t smem_u32(const void* p) {
    uint32_t a;
    asm("{ .reg .u64 t; cvta.to.shared.u64 t, %1; cvt.u32.u64 %0, t; }"
        : "=r"(a) : "l"(p));
    return a;
}

// ---------------------------------------------------------------------------
// Fused gathered bf16 MMA GEMM + online logsumexp partials.
// Block = 128 anchors x (NCHUNK*128) columns. 8 warps (4m x 2n), warp = 32m x 64n.
__global__ __launch_bounds__(256) void k_lse(const int* __restrict__ pa, int nPos) {
    int m0 = blockIdx.x * BM;
    int tid = threadIdx.x;
    int warp = tid >> 5;
    int lane = tid & 31;
    int warpm = warp >> 1;
    int warpn = warp & 1;

    __shared__ __align__(16) __nv_bfloat16 As[BM * BK];
    __shared__ __align__(16) __nv_bfloat16 Bs[BN * BK];
    __shared__ int arow[BM];

    if (tid < BM) {
        int p = m0 + tid;
        if (p >= nPos) p = nPos - 1;
        arow[tid] = pa[p];
    }
    __syncthreads();

    uint32_t As_base = smem_u32(As);
    uint32_t Bs_base = smem_u32(Bs);

    // running LSE state: u = mi*2 + h  (mi: 16-row block, h: 8-row half)
    float rmv[4];
    float rsv[4];
#pragma unroll
    for (int u = 0; u < 4; u++) { rmv[u] = -1e30f; rsv[u] = 0.0f; }

    for (int nc = 0; nc < NCHUNK; nc++) {
        int n0 = (blockIdx.y * NCHUNK + nc) * BN;

        // acc[(mi*8 + j)*4 + q]
        float acc[64];
#pragma unroll
        for (int q = 0; q < 64; q++) acc[q] = 0.0f;

        for (int k0 = 0; k0 < D; k0 += BK) {
            // Fill As (gathered) + Bs, 128-byte rows, XOR-16B swizzle.
#pragma unroll
            for (int it = 0; it < 4; it++) {
                int idx = it * 256 + tid;
                int r = idx >> 3;
                int c = idx & 7;
                int off = (r * 128 + c * 16) ^ ((r & 7) << 4);
                uint4 va = *(const uint4*)(g_eb + (size_t)arow[r] * D + k0 + c * 8);
                *(uint4*)((char*)As + off) = va;
                uint4 vb = *(const uint4*)(g_eb + (size_t)(n0 + r) * D + k0 + c * 8);
                *(uint4*)((char*)Bs + off) = vb;
            }
            __syncthreads();

#pragma unroll
            for (int kk = 0; kk < 4; kk++) {
                uint32_t afr0[4];
                uint32_t afr1[4];
                uint32_t bfr[4][4];
                {
                    int r = warpm * 32 + (lane & 15);
                    int off = (r * 128 + kk * 32 + (lane >> 4) * 16) ^ ((r & 7) << 4);
                    ldmatrix_x4(afr0, As_base + off);
                }
                {
                    int r = warpm * 32 + 16 + (lane & 15);
                    int off = (r * 128 + kk * 32 + (lane >> 4) * 16) ^ ((r & 7) << 4);
                    ldmatrix_x4(afr1, As_base + off);
                }
#pragma unroll
                for (int g = 0; g < 4; g++) {
                    int r = warpn * 64 + g * 16 + (lane & 15);
                    int off = (r * 128 + kk * 32 + (lane >> 4) * 16) ^ ((r & 7) << 4);
                    ldmatrix_x4(bfr[g], Bs_base + off);
                }
#pragma unroll
                for (int g = 0; g < 4; g++) {
                    mma16816(&acc[(0 * 8 + 2 * g + 0) * 4], afr0, bfr[g][0], bfr[g][2]);
                    mma16816(&acc[(0 * 8 + 2 * g + 1) * 4], afr0, bfr[g][1], bfr[g][3]);
                    mma16816(&acc[(1 * 8 + 2 * g + 0) * 4], afr1, bfr[g][0], bfr[g][2]);
                    mma16816(&acc[(1 * 8 + 2 * g + 1) * 4], afr1, bfr[g][1], bfr[g][3]);
                }
            }
            __syncthreads();
        }

        // Online LSE update for this 128-col chunk.
#pragma unroll
        for (int u = 0; u < 4; u++) {
            int mi = u >> 1;
            int h = u & 1;
            float vals[16];
#pragma unroll
            for (int j = 0; j < 8; j++) {
                vals[2 * j + 0] = acc[(mi * 8 + j) * 4 + h * 2 + 0] * INV_T;
                vals[2 * j + 1] = acc[(mi * 8 + j) * 4 + h * 2 + 1] * INV_T;
            }
            float vmax = vals[0];
#pragma unroll
            for (int q = 1; q < 16; q++) vmax = fmaxf(vmax, vals[q]);
            float ssum = 0.0f;
#pragma unroll
            for (int q = 0; q < 16; q++) ssum += __expf(vals[q] - vmax);
#pragma unroll
            for (int o = 1; o < 4; o <<= 1) {
                float mo = __shfl_xor_sync(0xffffffffu, vmax, o);
                float so = __shfl_xor_sync(0xffffffffu, ssum, o);
                float nmx = fmaxf(vmax, mo);
                ssum = ssum * __expf(vmax - nmx) + so * __expf(mo - nmx);
                vmax = nmx;
            }
            float nmx = fmaxf(rmv[u], vmax);
            rsv[u] = rsv[u] * __expf(rmv[u] - nmx) + ssum * __expf(vmax - nmx);
            rmv[u] = nmx;
        }
    }

    if ((lane & 3) == 0) {
        int slot = blockIdx.y * 2 + warpn;
#pragma unroll
        for (int u = 0; u < 4; u++) {
            int mi = u >> 1;
            int h = u & 1;
            int row = m0 + warpm * 32 + mi * 16 + h * 8 + (lane >> 2);
            if (row < nPos) {
                g_pm[row * NPART + slot] = rmv[u];
                g_ps[row * NPART + slot] = rsv[u];
            }
        }
    }
}

// ---------------------------------------------------------------------------
__global__ void k_rowlse(int nPos) {
    int p = blockIdx.x * blockDim.x + threadIdx.x;
    if (p >= nPos) return;
    float m = -1e30f;
    float s = 0.0f;
#pragma unroll
    for (int k = 0; k < NPART; k++) {
        float mk = g_pm[p * NPART + k];
        float sk = g_ps[p * NPART + k];
        float nmx = fmaxf(m, mk);
        s = s * __expf(m - nmx) + sk * __expf(mk - nmx);
        m = nmx;
    }
    g_rowloss[p] = m + logf(s) - g_posdot[p] * INV_T;
}

// ---------------------------------------------------------------------------
__global__ void k_finalize(float* __restrict__ outp, int nPos, int nNeg, int out_size) {
    int t = threadIdx.x;
    float lsum = 0.0f;
    float psum = 0.0f;
    float nsum = 0.0f;
    for (int p = t; p < nPos; p += 256) { lsum += g_rowloss[p]; psum += g_posdot[p]; }
    for (int p = t; p < nNeg; p += 256) nsum += g_negdot[p];
    __shared__ float rl[256];
    __shared__ float rp[256];
    __shared__ float rn[256];
    rl[t] = lsum; rp[t] = psum; rn[t] = nsum;
    __syncthreads();
    for (int o = 128; o; o >>= 1) {
        if (t < o) { rl[t] += rl[t + o]; rp[t] += rp[t + o]; rn[t] += rn[t + o]; }
        __syncthreads();
    }
    if (t == 0) {
        if (out_size > 0) outp[0] = rl[0] / (float)nPos;
        if (out_size > 1) outp[1] = rp[0] / (float)nPos;
        if (out_size > 2) outp[2] = rn[0] / (float)nNeg;
    }
}

// ---------------------------------------------------------------------------
extern "C" void kernel_launch(void* const* d_in, const int* in_sizes, int n_in,
                              void* d_out, int out_size) {
    const float* emb = (const float*)d_in[0];
    const int* pa = (const int*)d_in[1];
    const int* pt = (const int*)d_in[2];
    const int* na = (const int*)d_in[3];
    const int* nt = (const int*)d_in[4];
    int nPos = in_sizes[1];
    int nNeg = in_sizes[3];

    k_normalize<<<N_EMB, 128>>>(emb);

    int pairs = nPos + nNeg;
    int pblocks = (pairs * 32 + 255) / 256;
    k_pairdot<<<pblocks, 256>>>(pa, pt, na, nt, nPos, nNeg);

    dim3 grid((nPos + BM - 1) / BM, NSPLIT);
    k_lse<<<grid, 256>>>(pa, nPos);

    k_rowlse<<<(nPos + 127) / 128, 128>>>(nPos);
    k_finalize<<<1, 256>>>((float*)d_out, nPos, nNeg, out_size);
}

// round 4
// speedup vs baseline: 6.4050x; 1.7293x over previous
#include <cuda_runtime.h>
#include <cuda_bf16.h>
#include <math.h>
#include <stdint.h>

// Problem constants (fixed shapes for this problem id)
#define N_EMB   8192
#define D       512
#define P_MAX   4096
#define NEG_MAX 16384
#define INV_T   (1.0f / 0.07f)

// MMA LSE GEMM tiling
#define BM 128
#define BN 128
#define BK 64
#define KSTEPS (D / BK)
#define NSPLIT 16
#define NCHUNK 4
#define NPART  32

#define TILE_BYTES (BM * BK * 2)          // 16384 per matrix per stage
#define SMEM_DYN   (4 * TILE_BYTES)       // A0,A1,B0,B1 = 64 KB

// Scratch (device globals: allocation is forbidden)
__device__ float         g_e [N_EMB * D];
__device__ __nv_bfloat16 g_eb[N_EMB * D];
__device__ float g_pm[NPART * P_MAX];     // [slot][row] - coalesced combine
__device__ float g_ps[NPART * P_MAX];
__device__ float g_posdot [P_MAX];
__device__ float g_negdot [NEG_MAX];
__device__ float g_rowloss[P_MAX];

// ---------------------------------------------------------------------------
__global__ void k_normalize(const float* __restrict__ emb) {
    int row = blockIdx.x;
    int t = threadIdx.x;
    const float4* src = (const float4*)emb + row * (D / 4);
    float4 v = src[t];
    float ss = v.x * v.x + v.y * v.y + v.z * v.z + v.w * v.w;
#pragma unroll
    for (int o = 16; o; o >>= 1) ss += __shfl_xor_sync(0xffffffffu, ss, o);
    __shared__ float red[4];
    if ((t & 31) == 0) red[t >> 5] = ss;
    __syncthreads();
    float tot = red[0] + red[1] + red[2] + red[3];
    float inv = 1.0f / fmaxf(sqrtf(tot), 1e-8f);
    v.x *= inv; v.y *= inv; v.z *= inv; v.w *= inv;
    ((float4*)g_e)[row * (D / 4) + t] = v;
    __nv_bfloat162 b0 = __floats2bfloat162_rn(v.x, v.y);
    __nv_bfloat162 b1 = __floats2bfloat162_rn(v.z, v.w);
    ((__nv_bfloat162*)g_eb)[row * (D / 2) + t * 2 + 0] = b0;
    ((__nv_bfloat162*)g_eb)[row * (D / 2) + t * 2 + 1] = b1;
}

// ---------------------------------------------------------------------------
__global__ void k_pairdot(const int* __restrict__ pa, const int* __restrict__ pt,
                          const int* __restrict__ na, const int* __restrict__ nt,
                          int nPos, int nNeg) {
    int warp = (blockIdx.x * blockDim.x + threadIdx.x) >> 5;
    int lane = threadIdx.x & 31;
    if (warp >= nPos + nNeg) return;
    int a, b;
    float* outp;
    if (warp < nPos) {
        a = pa[warp]; b = pt[warp]; outp = &g_posdot[warp];
    } else {
        int w = warp - nPos;
        a = na[w]; b = nt[w]; outp = &g_negdot[w];
    }
    const float4* va = (const float4*)(g_e + (size_t)a * D);
    const float4* vb = (const float4*)(g_e + (size_t)b * D);
    float s = 0.0f;
#pragma unroll 4
    for (int i = lane; i < D / 4; i += 32) {
        float4 x = va[i];
        float4 y = vb[i];
        s += x.x * y.x + x.y * y.y + x.z * y.z + x.w * y.w;
    }
#pragma unroll
    for (int o = 16; o; o >>= 1) s += __shfl_xor_sync(0xffffffffu, s, o);
    if (lane == 0) *outp = s;
}

// ---------------------------------------------------------------------------
__device__ __forceinline__ void ldmatrix_x4(uint32_t* d, uint32_t addr) {
    asm volatile("ldmatrix.sync.aligned.m8n8.x4.shared.b16 {%0,%1,%2,%3}, [%4];"
                 : "=r"(d[0]), "=r"(d[1]), "=r"(d[2]), "=r"(d[3]) : "r"(addr));
}
__device__ __forceinline__ void mma16816(float* c, const uint32_t* a,
                                         uint32_t b0, uint32_t b1) {
    asm volatile("mma.sync.aligned.m16n8k16.row.col.f32.bf16.bf16.f32 "
                 "{%0,%1,%2,%3}, {%4,%5,%6,%7}, {%8,%9}, {%0,%1,%2,%3};"
                 : "+f"(c[0]), "+f"(c[1]), "+f"(c[2]), "+f"(c[3])
                 : "r"(a[0]), "r"(a[1]), "r"(a[2]), "r"(a[3]), "r"(b0), "r"(b1));
}
__device__ __forceinline__ uint32_t smem_u32(const void* p) {
    uint32_t a;
    asm("{ .reg .u64 t; cvta.to.shared.u64 t, %1; cvt.u32.u64 %0, t; }"
        : "=r"(a) : "l"(p));
    return a;
}
__device__ __forceinline__ void cp_async16(uint32_t smem_addr, const void* gptr) {
    asm volatile("cp.async.cg.shared.global [%0], [%1], 16;"
                 :: "r"(smem_addr), "l"(gptr));
}
__device__ __forceinline__ void cp_commit() {
    asm volatile("cp.async.commit_group;");
}
template <int N>
__device__ __forceinline__ void cp_wait() {
    asm volatile("cp.async.wait_group %0;" :: "n"(N));
}

// ---------------------------------------------------------------------------
// Fused gathered bf16 MMA GEMM + online LSE, cp.async 2-stage pipelined.
// Block = 128 anchors x (NCHUNK*128) columns. 8 warps (4m x 2n), warp 32m x 64n.
__global__ __launch_bounds__(256) void k_lse(const int* __restrict__ pa, int nPos) {
    extern __shared__ __align__(16) char dynsmem[];
    // layout: As[2][16384], Bs[2][16384]
    char* As_ptr = dynsmem;
    char* Bs_ptr = dynsmem + 2 * TILE_BYTES;

    __shared__ int arow[BM];

    int m0 = blockIdx.x * BM;
    int tid = threadIdx.x;
    int warp = tid >> 5;
    int lane = tid & 31;
    int warpm = warp >> 1;
    int warpn = warp & 1;

    if (tid < BM) {
        int p = m0 + tid;
        if (p >= nPos) p = nPos - 1;
        arow[tid] = pa[p];
    }
    __syncthreads();

    uint32_t As_base = smem_u32(As_ptr);
    uint32_t Bs_base = smem_u32(Bs_ptr);

    float rmv[4];
    float rsv[4];
#pragma unroll
    for (int u = 0; u < 4; u++) { rmv[u] = -1e30f; rsv[u] = 0.0f; }

    for (int nc = 0; nc < NCHUNK; nc++) {
        int n0 = (blockIdx.y * NCHUNK + nc) * BN;

        float acc[64];
#pragma unroll
        for (int q = 0; q < 64; q++) acc[q] = 0.0f;

        // ---- stage-load lambda (manually inlined twice) ----
        // per stage: 1024 uint4 per matrix; 4 iters x 256 thr, A+B each iter.
#pragma unroll
        for (int it = 0; it < 4; it++) {           // preload stage 0, k0 = 0
            int idx = it * 256 + tid;
            int r = idx >> 3;
            int c = idx & 7;
            int off = (r * 128 + c * 16) ^ ((r & 7) << 4);
            cp_async16(As_base + off, g_eb + (size_t)arow[r] * D + c * 8);
            cp_async16(Bs_base + off, g_eb + (size_t)(n0 + r) * D + c * 8);
        }
        cp_commit();

        for (int s = 0; s < KSTEPS; s++) {
            int cur = s & 1;
            if (s + 1 < KSTEPS) {
                int nxt = (s + 1) & 1;
                int k0n = (s + 1) * BK;
                uint32_t An = As_base + nxt * TILE_BYTES;
                uint32_t Bn = Bs_base + nxt * TILE_BYTES;
#pragma unroll
                for (int it = 0; it < 4; it++) {
                    int idx = it * 256 + tid;
                    int r = idx >> 3;
                    int c = idx & 7;
                    int off = (r * 128 + c * 16) ^ ((r & 7) << 4);
                    cp_async16(An + off, g_eb + (size_t)arow[r] * D + k0n + c * 8);
                    cp_async16(Bn + off, g_eb + (size_t)(n0 + r) * D + k0n + c * 8);
                }
                cp_commit();
                cp_wait<1>();
            } else {
                cp_wait<0>();
            }
            __syncthreads();

            uint32_t Ac = As_base + cur * TILE_BYTES;
            uint32_t Bc = Bs_base + cur * TILE_BYTES;
#pragma unroll
            for (int kk = 0; kk < 4; kk++) {
                uint32_t afr0[4];
                uint32_t afr1[4];
                uint32_t bfr[4][4];
                {
                    int r = warpm * 32 + (lane & 15);
                    int off = (r * 128 + kk * 32 + (lane >> 4) * 16) ^ ((r & 7) << 4);
                    ldmatrix_x4(afr0, Ac + off);
                }
                {
                    int r = warpm * 32 + 16 + (lane & 15);
                    int off = (r * 128 + kk * 32 + (lane >> 4) * 16) ^ ((r & 7) << 4);
                    ldmatrix_x4(afr1, Ac + off);
                }
#pragma unroll
                for (int g = 0; g < 4; g++) {
                    int r = warpn * 64 + g * 16 + (lane & 15);
                    int off = (r * 128 + kk * 32 + (lane >> 4) * 16) ^ ((r & 7) << 4);
                    ldmatrix_x4(bfr[g], Bc + off);
                }
#pragma unroll
                for (int g = 0; g < 4; g++) {
                    mma16816(&acc[(2 * g + 0) * 4], afr0, bfr[g][0], bfr[g][2]);
                    mma16816(&acc[(2 * g + 1) * 4], afr0, bfr[g][1], bfr[g][3]);
                    mma16816(&acc[(8 + 2 * g + 0) * 4], afr1, bfr[g][0], bfr[g][2]);
                    mma16816(&acc[(8 + 2 * g + 1) * 4], afr1, bfr[g][1], bfr[g][3]);
                }
            }
            __syncthreads();  // compute done before next-next load overwrites
        }

        // Online LSE update for this 128-col chunk.
#pragma unroll
        for (int u = 0; u < 4; u++) {
            int mi = u >> 1;
            int h = u & 1;
            float vals[16];
#pragma unroll
            for (int j = 0; j < 8; j++) {
                vals[2 * j + 0] = acc[(mi * 8 + j) * 4 + h * 2 + 0] * INV_T;
                vals[2 * j + 1] = acc[(mi * 8 + j) * 4 + h * 2 + 1] * INV_T;
            }
            float vmax = vals[0];
#pragma unroll
            for (int q = 1; q < 16; q++) vmax = fmaxf(vmax, vals[q]);
            float ssum = 0.0f;
#pragma unroll
            for (int q = 0; q < 16; q++) ssum += __expf(vals[q] - vmax);
#pragma unroll
            for (int o = 1; o < 4; o <<= 1) {
                float mo = __shfl_xor_sync(0xffffffffu, vmax, o);
                float so = __shfl_xor_sync(0xffffffffu, ssum, o);
                float nmx = fmaxf(vmax, mo);
                ssum = ssum * __expf(vmax - nmx) + so * __expf(mo - nmx);
                vmax = nmx;
            }
            float nmx = fmaxf(rmv[u], vmax);
            rsv[u] = rsv[u] * __expf(rmv[u] - nmx) + ssum * __expf(vmax - nmx);
            rmv[u] = nmx;
        }
    }

    if ((lane & 3) == 0) {
        int slot = blockIdx.y * 2 + warpn;
#pragma unroll
        for (int u = 0; u < 4; u++) {
            int mi = u >> 1;
            int h = u & 1;
            int row = m0 + warpm * 32 + mi * 16 + h * 8 + (lane >> 2);
            if (row < nPos) {
                g_pm[slot * P_MAX + row] = rmv[u];
                g_ps[slot * P_MAX + row] = rsv[u];
            }
        }
    }
}

// ---------------------------------------------------------------------------
__global__ void k_rowlse(int nPos) {
    int p = blockIdx.x * blockDim.x + threadIdx.x;
    if (p >= nPos) return;
    float m = -1e30f;
    float s = 0.0f;
#pragma unroll
    for (int k = 0; k < NPART; k++) {
        float mk = g_pm[k * P_MAX + p];
        float sk = g_ps[k * P_MAX + p];
        float nmx = fmaxf(m, mk);
        s = s * __expf(m - nmx) + sk * __expf(mk - nmx);
        m = nmx;
    }
    g_rowloss[p] = m + logf(s) - g_posdot[p] * INV_T;
}

// ---------------------------------------------------------------------------
__global__ void k_finalize(float* __restrict__ outp, int nPos, int nNeg, int out_size) {
    int t = threadIdx.x;
    float lsum = 0.0f;
    float psum = 0.0f;
    float nsum = 0.0f;
    for (int p = t; p < nPos; p += 256) { lsum += g_rowloss[p]; psum += g_posdot[p]; }
    for (int p = t; p < nNeg; p += 256) nsum += g_negdot[p];
    __shared__ float rl[256];
    __shared__ float rp[256];
    __shared__ float rn[256];
    rl[t] = lsum; rp[t] = psum; rn[t] = nsum;
    __syncthreads();
    for (int o = 128; o; o >>= 1) {
        if (t < o) { rl[t] += rl[t + o]; rp[t] += rp[t + o]; rn[t] += rn[t + o]; }
        __syncthreads();
    }
    if (t == 0) {
        if (out_size > 0) outp[0] = rl[0] / (float)nPos;
        if (out_size > 1) outp[1] = rp[0] / (float)nPos;
        if (out_size > 2) outp[2] = rn[0] / (float)nNeg;
    }
}

// ---------------------------------------------------------------------------
extern "C" void kernel_launch(void* const* d_in, const int* in_sizes, int n_in,
                              void* d_out, int out_size) {
    const float* emb = (const float*)d_in[0];
    const int* pa = (const int*)d_in[1];
    const int* pt = (const int*)d_in[2];
    const int* na = (const int*)d_in[3];
    const int* nt = (const int*)d_in[4];
    int nPos = in_sizes[1];
    int nNeg = in_sizes[3];

    cudaFuncSetAttribute(k_lse, cudaFuncAttributeMaxDynamicSharedMemorySize, SMEM_DYN);

    k_normalize<<<N_EMB, 128>>>(emb);

    int pairs = nPos + nNeg;
    int pblocks = (pairs * 32 + 255) / 256;
    k_pairdot<<<pblocks, 256>>>(pa, pt, na, nt, nPos, nNeg);

    dim3 grid((nPos + BM - 1) / BM, NSPLIT);
    k_lse<<<grid, 256, SMEM_DYN>>>(pa, nPos);

    k_rowlse<<<(nPos + 127) / 128, 128>>>(nPos);
    k_finalize<<<1, 256>>>((float*)d_out, nPos, nNeg, out_size);
}

// round 6
// speedup vs baseline: 6.4300x; 1.0039x over previous
#include <cuda_runtime.h>
#include <cuda_bf16.h>
#include <math.h>
#include <stdint.h>

// Problem constants
#define N_EMB   8192
#define D       512
#define P_MAX   4096
#define NEG_MAX 16384
#define INV_T   (1.0f / 0.07f)

// LSE GEMM config: BM=128, BN=256, BK=64, warp tile 64x64, 8 warps (2m x 4n)
#define BM 128
#define BN 256
#define BK 64
#define NSPLIT 4
#define CHUNKS 8                    // per CTA: 8 chunks x 256 = 2048 cols
#define SLABS  (CHUNKS * (D / BK))  // 64
#define NPART  NSPLIT

#define A_STAGE (BM * BK * 2)       // 16384
#define B_STAGE (BN * BK * 2)       // 32768
#define NSTAGE  3
#define SMEM_DYN (NSTAGE * (A_STAGE + B_STAGE))   // 147456

// Scratch (device globals: allocation is forbidden)
__device__ float         g_e [N_EMB * D];
__device__ __nv_bfloat16 g_eb[N_EMB * D];
__device__ float g_pm[NPART * P_MAX];
__device__ float g_ps[NPART * P_MAX];
__device__ float g_posdot [P_MAX];
__device__ float g_negdot [NEG_MAX];
__device__ float g_rowloss[P_MAX];

// ---------------------------------------------------------------------------
__global__ void k_normalize(const float* __restrict__ emb) {
    int row = blockIdx.x;
    int t = threadIdx.x;
    const float4* src = (const float4*)emb + row * (D / 4);
    float4 v = src[t];
    float ss = v.x * v.x + v.y * v.y + v.z * v.z + v.w * v.w;
#pragma unroll
    for (int o = 16; o; o >>= 1) ss += __shfl_xor_sync(0xffffffffu, ss, o);
    __shared__ float red[4];
    if ((t & 31) == 0) red[t >> 5] = ss;
    __syncthreads();
    float tot = red[0] + red[1] + red[2] + red[3];
    float inv = 1.0f / fmaxf(sqrtf(tot), 1e-8f);
    v.x *= inv; v.y *= inv; v.z *= inv; v.w *= inv;
    ((float4*)g_e)[row * (D / 4) + t] = v;
    __nv_bfloat162 b0 = __floats2bfloat162_rn(v.x, v.y);
    __nv_bfloat162 b1 = __floats2bfloat162_rn(v.z, v.w);
    ((__nv_bfloat162*)g_eb)[row * (D / 2) + t * 2 + 0] = b0;
    ((__nv_bfloat162*)g_eb)[row * (D / 2) + t * 2 + 1] = b1;
}

// ---------------------------------------------------------------------------
__global__ void k_pairdot(const int* __restrict__ pa, const int* __restrict__ pt,
                          const int* __restrict__ na, const int* __restrict__ nt,
                          int nPos, int nNeg) {
    int warp = (blockIdx.x * blockDim.x + threadIdx.x) >> 5;
    int lane = threadIdx.x & 31;
    if (warp >= nPos + nNeg) return;
    int a, b;
    float* outp;
    if (warp < nPos) {
        a = pa[warp]; b = pt[warp]; outp = &g_posdot[warp];
    } else {
        int w = warp - nPos;
        a = na[w]; b = nt[w]; outp = &g_negdot[w];
    }
    const float4* va = (const float4*)(g_e + (size_t)a * D);
    const float4* vb = (const float4*)(g_e + (size_t)b * D);
    float s = 0.0f;
#pragma unroll 4
    for (int i = lane; i < D / 4; i += 32) {
        float4 x = va[i];
        float4 y = vb[i];
        s += x.x * y.x + x.y * y.y + x.z * y.z + x.w * y.w;
    }
#pragma unroll
    for (int o = 16; o; o >>= 1) s += __shfl_xor_sync(0xffffffffu, s, o);
    if (lane == 0) *outp = s;
}

// ---------------------------------------------------------------------------
__device__ __forceinline__ void ldmatrix_x4(uint32_t* d, uint32_t addr) {
    asm volatile("ldmatrix.sync.aligned.m8n8.x4.shared.b16 {%0,%1,%2,%3}, [%4];"
                 : "=r"(d[0]), "=r"(d[1]), "=r"(d[2]), "=r"(d[3]) : "r"(addr));
}
__device__ __forceinline__ void mma16816(float* c, const uint32_t* a,
                                         uint32_t b0, uint32_t b1) {
    asm volatile("mma.sync.aligned.m16n8k16.row.col.f32.bf16.bf16.f32 "
                 "{%0,%1,%2,%3}, {%4,%5,%6,%7}, {%8,%9}, {%0,%1,%2,%3};"
                 : "+f"(c[0]), "+f"(c[1]), "+f"(c[2]), "+f"(c[3])
                 : "r"(a[0]), "r"(a[1]), "r"(a[2]), "r"(a[3]), "r"(b0), "r"(b1));
}
__device__ __forceinline__ uint32_t smem_u32(const void* p) {
    uint32_t a;
    asm("{ .reg .u64 t; cvta.to.shared.u64 t, %1; cvt.u32.u64 %0, t; }"
        : "=r"(a) : "l"(p));
    return a;
}
__device__ __forceinline__ void cp_async16(uint32_t smem_addr, const void* gptr) {
    asm volatile("cp.async.cg.shared.global [%0], [%1], 16;"
                 :: "r"(smem_addr), "l"(gptr));
}
__device__ __forceinline__ void cp_commit() {
    asm volatile("cp.async.commit_group;");
}
template <int N>
__device__ __forceinline__ void cp_wait() {
    asm volatile("cp.async.wait_group %0;" :: "n"(N) : "memory");
}

// ---------------------------------------------------------------------------
// Fused gathered bf16 MMA GEMM + online LSE. 3-stage cp.async ring, one
// syncthreads per K-slab (issue-after-sync makes the 3-buffer ring race-free).
__global__ __launch_bounds__(256, 1) void k_lse(const int* __restrict__ pa, int nPos) {
    extern __shared__ __align__(16) char dsm[];
    uint32_t a_base = smem_u32(dsm);                       // 3 x 16KB
    uint32_t b_base = a_base + NSTAGE * A_STAGE;           // 3 x 32KB

    __shared__ int arow[BM];
    __shared__ float pm_s[4][BM];
    __shared__ float ps_s[4][BM];

    int tid = threadIdx.x;
    int warp = tid >> 5;
    int lane = tid & 31;
    int warpm = warp >> 2;       // 0..1 (64-row half)
    int warpn = warp & 3;        // 0..3 (64-col quarter)
    int m0 = blockIdx.x * BM;
    int n_base = blockIdx.y * (CHUNKS * BN);

    if (tid < BM) {
        int p = m0 + tid;
        if (p >= nPos) p = nPos - 1;
        arow[tid] = pa[p];
    }
    __syncthreads();

    // ---- slab loader: A 128x64 + B 256x64 into stage buf ----
    auto load_slab = [&](int t) {
        int c = t >> 3;
        int kp = t & 7;
        int k0 = kp * BK;
        int n0 = n_base + c * BN;
        uint32_t Ab = a_base + (t % NSTAGE) * A_STAGE;
        uint32_t Bb = b_base + (t % NSTAGE) * B_STAGE;
#pragma unroll
        for (int it = 0; it < 4; it++) {          // A: 1024 x 16B
            int id = it * 256 + tid;
            int r = id >> 3;
            int ci = id & 7;
            uint32_t off = ((uint32_t)r * 128u + (uint32_t)ci * 16u)
                         ^ ((uint32_t)(r & 7) << 4);
            cp_async16(Ab + off, g_eb + (size_t)arow[r] * D + k0 + ci * 8);
        }
#pragma unroll
        for (int it = 0; it < 8; it++) {          // B: 2048 x 16B
            int id = it * 256 + tid;
            int r = id >> 3;
            int ci = id & 7;
            uint32_t off = ((uint32_t)r * 128u + (uint32_t)ci * 16u)
                         ^ ((uint32_t)(r & 7) << 4);
            cp_async16(Bb + off, g_eb + (size_t)(n0 + r) * D + k0 + ci * 8);
        }
        cp_commit();
    };

    float rmv[8];
    float rsv[8];
#pragma unroll
    for (int u = 0; u < 8; u++) { rmv[u] = -1e30f; rsv[u] = 0.0f; }

    float acc[128];
#pragma unroll
    for (int q = 0; q < 128; q++) acc[q] = 0.0f;

    load_slab(0);
    load_slab(1);

    for (int t = 0; t < SLABS; t++) {
        if (t < SLABS - 1) cp_wait<1>(); else cp_wait<0>();
        __syncthreads();
        if (t + 2 < SLABS) load_slab(t + 2);

        uint32_t Ab = a_base + (t % NSTAGE) * A_STAGE;
        uint32_t Bb = b_base + (t % NSTAGE) * B_STAGE;
#pragma unroll
        for (int kk = 0; kk < 4; kk++) {
            uint32_t afr[4][4];
            uint32_t bfr[4][4];
#pragma unroll
            for (int mi = 0; mi < 4; mi++) {
                int r = warpm * 64 + mi * 16 + (lane & 15);
                uint32_t off = ((uint32_t)r * 128u + (uint32_t)kk * 32u
                               + (uint32_t)(lane >> 4) * 16u)
                             ^ ((uint32_t)(r & 7) << 4);
                ldmatrix_x4(afr[mi], Ab + off);
            }
#pragma unroll
            for (int g = 0; g < 4; g++) {
                int r = warpn * 64 + g * 16 + (lane & 15);
                uint32_t off = ((uint32_t)r * 128u + (uint32_t)kk * 32u
                               + (uint32_t)(lane >> 4) * 16u)
                             ^ ((uint32_t)(r & 7) << 4);
                ldmatrix_x4(bfr[g], Bb + off);
            }
#pragma unroll
            for (int mi = 0; mi < 4; mi++) {
#pragma unroll
                for (int g = 0; g < 4; g++) {
                    mma16816(&acc[((mi * 4 + g) * 2 + 0) * 4], afr[mi],
                             bfr[g][0], bfr[g][2]);
                    mma16816(&acc[((mi * 4 + g) * 2 + 1) * 4], afr[mi],
                             bfr[g][1], bfr[g][3]);
                }
            }
        }

        if ((t & 7) == 7) {
            // ---- epilogue for chunk t>>3: online LSE over 256 cols ----
#pragma unroll
            for (int u = 0; u < 8; u++) {
                int mi = u >> 1;
                int h = u & 1;
                float vmax = -1e30f;
                float vals[16];
#pragma unroll
                for (int g = 0; g < 4; g++) {
#pragma unroll
                    for (int nh = 0; nh < 2; nh++) {
                        int bse = ((mi * 4 + g) * 2 + nh) * 4 + h * 2;
                        vals[g * 4 + nh * 2 + 0] = acc[bse + 0] * INV_T;
                        vals[g * 4 + nh * 2 + 1] = acc[bse + 1] * INV_T;
                    }
                }
#pragma unroll
                for (int q = 0; q < 16; q++) vmax = fmaxf(vmax, vals[q]);
                float vsum = 0.0f;
#pragma unroll
                for (int q = 0; q < 16; q++) vsum += __expf(vals[q] - vmax);
#pragma unroll
                for (int o = 1; o < 4; o <<= 1) {
                    float mo = __shfl_xor_sync(0xffffffffu, vmax, o);
                    float so = __shfl_xor_sync(0xffffffffu, vsum, o);
                    float nm = fmaxf(vmax, mo);
                    vsum = vsum * __expf(vmax - nm) + so * __expf(mo - nm);
                    vmax = nm;
                }
                if ((lane & 3) == 0) {
                    int lr = warpm * 64 + mi * 16 + h * 8 + (lane >> 2);
                    pm_s[warpn][lr] = vmax;
                    ps_s[warpn][lr] = vsum;
                }
            }
            __syncthreads();
            if (warpn == 0) {
#pragma unroll
                for (int u = 0; u < 8; u++) {
                    int mi = u >> 1;
                    int h = u & 1;
                    int lr = warpm * 64 + mi * 16 + h * 8 + (lane >> 2);
                    float m = pm_s[0][lr];
                    float s = ps_s[0][lr];
#pragma unroll
                    for (int w = 1; w < 4; w++) {
                        float mo = pm_s[w][lr];
                        float so = ps_s[w][lr];
                        float nm = fmaxf(m, mo);
                        s = s * __expf(m - nm) + so * __expf(mo - nm);
                        m = nm;
                    }
                    float nr = fmaxf(rmv[u], m);
                    rsv[u] = rsv[u] * __expf(rmv[u] - nr) + s * __expf(m - nr);
                    rmv[u] = nr;
                }
            }
            __syncthreads();
#pragma unroll
            for (int q = 0; q < 128; q++) acc[q] = 0.0f;
        }
    }

    if (warpn == 0 && (lane & 3) == 0) {
#pragma unroll
        for (int u = 0; u < 8; u++) {
            int mi = u >> 1;
            int h = u & 1;
            int row = m0 + warpm * 64 + mi * 16 + h * 8 + (lane >> 2);
            if (row < nPos) {
                g_pm[blockIdx.y * P_MAX + row] = rmv[u];
                g_ps[blockIdx.y * P_MAX + row] = rsv[u];
            }
        }
    }
}

// ---------------------------------------------------------------------------
__global__ void k_rowlse(int nPos) {
    int p = blockIdx.x * blockDim.x + threadIdx.x;
    if (p >= nPos) return;
    float m = -1e30f;
    float s = 0.0f;
#pragma unroll
    for (int k = 0; k < NPART; k++) {
        float mk = g_pm[k * P_MAX + p];
        float sk = g_ps[k * P_MAX + p];
        float nmx = fmaxf(m, mk);
        s = s * __expf(m - nmx) + sk * __expf(mk - nmx);
        m = nmx;
    }
    g_rowloss[p] = m + logf(s) - g_posdot[p] * INV_T;
}

// ---------------------------------------------------------------------------
__global__ void k_finalize(float* __restrict__ outp, int nPos, int nNeg, int out_size) {
    int t = threadIdx.x;
    float lsum = 0.0f;
    float psum = 0.0f;
    float nsum = 0.0f;
    for (int p = t; p < nPos; p += 256) { lsum += g_rowloss[p]; psum += g_posdot[p]; }
    for (int p = t; p < nNeg; p += 256) nsum += g_negdot[p];
    __shared__ float rl[256];
    __shared__ float rp[256];
    __shared__ float rn[256];
    rl[t] = lsum; rp[t] = psum; rn[t] = nsum;
    __syncthreads();
    for (int o = 128; o; o >>= 1) {
        if (t < o) { rl[t] += rl[t + o]; rp[t] += rp[t + o]; rn[t] += rn[t + o]; }
        __syncthreads();
    }
    if (t == 0) {
        if (out_size > 0) outp[0] = rl[0] / (float)nPos;
        if (out_size > 1) outp[1] = rp[0] / (float)nPos;
        if (out_size > 2) outp[2] = rn[0] / (float)nNeg;
    }
}

// ---------------------------------------------------------------------------
extern "C" void kernel_launch(void* const* d_in, const int* in_sizes, int n_in,
                              void* d_out, int out_size) {
    const float* emb = (const float*)d_in[0];
    const int* pa = (const int*)d_in[1];
    const int* pt = (const int*)d_in[2];
    const int* na = (const int*)d_in[3];
    const int* nt = (const int*)d_in[4];
    int nPos = in_sizes[1];
    int nNeg = in_sizes[3];

    cudaFuncSetAttribute(k_lse, cudaFuncAttributeMaxDynamicSharedMemorySize, SMEM_DYN);

    k_normalize<<<N_EMB, 128>>>(emb);

    int pairs = nPos + nNeg;
    int pblocks = (pairs * 32 + 255) / 256;
    k_pairdot<<<pblocks, 256>>>(pa, pt, na, nt, nPos, nNeg);

    dim3 grid((nPos + BM - 1) / BM, NSPLIT);
    k_lse<<<grid, 256, SMEM_DYN>>>(pa, nPos);

    k_rowlse<<<(nPos + 127) / 128, 128>>>(nPos);
    k_finalize<<<1, 256>>>((float*)d_out, nPos, nNeg, out_size);
}

// round 7
// speedup vs baseline: 6.6106x; 1.0281x over previous
#include <cuda_runtime.h>
#include <cuda_bf16.h>
#include <math.h>
#include <stdint.h>

// Problem constants
#define N_EMB   8192
#define D       512
#define P_MAX   4096
#define NEG_MAX 16384
#define INV_T   (1.0f / 0.07f)

// LSE GEMM: BM=128, BN=128, BK=64, 8 warps (4m x 2n), warp tile 32x64
#define BM 128
#define BN 128
#define BK 64
#define NSPLIT 8
#define CHUNKS 8                    // per CTA: 8 chunks x 128 = 1024 cols
#define SLABS  (CHUNKS * (D / BK))  // 64
#define NPART  NSPLIT

#define A_STAGE (BM * BK * 2)       // 16384
#define B_STAGE (BN * BK * 2)       // 16384
#define NSTAGE  3
#define SMEM_DYN (NSTAGE * (A_STAGE + B_STAGE))   // 98304

// Scratch (device globals: allocation is forbidden)
__device__ float         g_e [N_EMB * D];
__device__ __nv_bfloat16 g_eb[N_EMB * D];
__device__ float g_pm[NPART * P_MAX];
__device__ float g_ps[NPART * P_MAX];
__device__ float g_posdot [P_MAX];
__device__ float g_negdot [NEG_MAX];
__device__ float g_part_l[32];
__device__ float g_part_p[32];
__device__ float g_part_n[32];

// ---------------------------------------------------------------------------
__global__ void k_normalize(const float* __restrict__ emb) {
    int row = blockIdx.x;
    int t = threadIdx.x;
    const float4* src = (const float4*)emb + row * (D / 4);
    float4 v = src[t];
    float ss = v.x * v.x + v.y * v.y + v.z * v.z + v.w * v.w;
#pragma unroll
    for (int o = 16; o; o >>= 1) ss += __shfl_xor_sync(0xffffffffu, ss, o);
    __shared__ float red[4];
    if ((t & 31) == 0) red[t >> 5] = ss;
    __syncthreads();
    float tot = red[0] + red[1] + red[2] + red[3];
    float inv = 1.0f / fmaxf(sqrtf(tot), 1e-8f);
    v.x *= inv; v.y *= inv; v.z *= inv; v.w *= inv;
    ((float4*)g_e)[row * (D / 4) + t] = v;
    __nv_bfloat162 b0 = __floats2bfloat162_rn(v.x, v.y);
    __nv_bfloat162 b1 = __floats2bfloat162_rn(v.z, v.w);
    ((__nv_bfloat162*)g_eb)[row * (D / 2) + t * 2 + 0] = b0;
    ((__nv_bfloat162*)g_eb)[row * (D / 2) + t * 2 + 1] = b1;
}

// ---------------------------------------------------------------------------
__global__ void k_pairdot(const int* __restrict__ pa, const int* __restrict__ pt,
                          const int* __restrict__ na, const int* __restrict__ nt,
                          int nPos, int nNeg) {
    int warp = (blockIdx.x * blockDim.x + threadIdx.x) >> 5;
    int lane = threadIdx.x & 31;
    if (warp >= nPos + nNeg) return;
    int a, b;
    float* outp;
    if (warp < nPos) {
        a = pa[warp]; b = pt[warp]; outp = &g_posdot[warp];
    } else {
        int w = warp - nPos;
        a = na[w]; b = nt[w]; outp = &g_negdot[w];
    }
    const float4* va = (const float4*)(g_e + (size_t)a * D);
    const float4* vb = (const float4*)(g_e + (size_t)b * D);
    float s = 0.0f;
#pragma unroll 4
    for (int i = lane; i < D / 4; i += 32) {
        float4 x = va[i];
        float4 y = vb[i];
        s += x.x * y.x + x.y * y.y + x.z * y.z + x.w * y.w;
    }
#pragma unroll
    for (int o = 16; o; o >>= 1) s += __shfl_xor_sync(0xffffffffu, s, o);
    if (lane == 0) *outp = s;
}

// ---------------------------------------------------------------------------
__device__ __forceinline__ void ldmatrix_x4(uint32_t* d, uint32_t addr) {
    asm volatile("ldmatrix.sync.aligned.m8n8.x4.shared.b16 {%0,%1,%2,%3}, [%4];"
                 : "=r"(d[0]), "=r"(d[1]), "=r"(d[2]), "=r"(d[3]) : "r"(addr));
}
__device__ __forceinline__ void mma16816(float* c, const uint32_t* a,
                                         uint32_t b0, uint32_t b1) {
    asm volatile("mma.sync.aligned.m16n8k16.row.col.f32.bf16.bf16.f32 "
                 "{%0,%1,%2,%3}, {%4,%5,%6,%7}, {%8,%9}, {%0,%1,%2,%3};"
                 : "+f"(c[0]), "+f"(c[1]), "+f"(c[2]), "+f"(c[3])
                 : "r"(a[0]), "r"(a[1]), "r"(a[2]), "r"(a[3]), "r"(b0), "r"(b1));
}
__device__ __forceinline__ uint32_t smem_u32(const void* p) {
    uint32_t a;
    asm("{ .reg .u64 t; cvta.to.shared.u64 t, %1; cvt.u32.u64 %0, t; }"
        : "=r"(a) : "l"(p));
    return a;
}
__device__ __forceinline__ void cp_async16(uint32_t smem_addr, const void* gptr) {
    asm volatile("cp.async.cg.shared.global [%0], [%1], 16;"
                 :: "r"(smem_addr), "l"(gptr));
}
__device__ __forceinline__ void cp_commit() {
    asm volatile("cp.async.commit_group;");
}
template <int N>
__device__ __forceinline__ void cp_wait() {
    asm volatile("cp.async.wait_group %0;" :: "n"(N) : "memory");
}

// ---------------------------------------------------------------------------
// Fused gathered bf16 MMA GEMM + online LSE. 3-stage ring, one sync per slab,
// 2 CTAs/SM for HMMA latency hiding.
__global__ __launch_bounds__(256, 2) void k_lse(const int* __restrict__ pa, int nPos) {
    extern __shared__ __align__(16) char dsm[];
    uint32_t a_base = smem_u32(dsm);
    uint32_t b_base = a_base + NSTAGE * A_STAGE;

    __shared__ int arow[BM];
    __shared__ float pm_s[2][BM];
    __shared__ float ps_s[2][BM];

    int tid = threadIdx.x;
    int warp = tid >> 5;
    int lane = tid & 31;
    int warpm = warp >> 1;       // 0..3 (32-row group)
    int warpn = warp & 1;        // 0..1 (64-col half)
    int m0 = blockIdx.x * BM;
    int n_base = blockIdx.y * (CHUNKS * BN);

    if (tid < BM) {
        int p = m0 + tid;
        if (p >= nPos) p = nPos - 1;
        arow[tid] = pa[p];
    }
    __syncthreads();

    auto load_slab = [&](int t) {
        int c = t >> 3;
        int kp = t & 7;
        int k0 = kp * BK;
        int n0 = n_base + c * BN;
        uint32_t Ab = a_base + (t % NSTAGE) * A_STAGE;
        uint32_t Bb = b_base + (t % NSTAGE) * B_STAGE;
#pragma unroll
        for (int it = 0; it < 4; it++) {
            int id = it * 256 + tid;
            int r = id >> 3;
            int ci = id & 7;
            uint32_t off = ((uint32_t)r * 128u + (uint32_t)ci * 16u)
                         ^ ((uint32_t)(r & 7) << 4);
            cp_async16(Ab + off, g_eb + (size_t)arow[r] * D + k0 + ci * 8);
            cp_async16(Bb + off, g_eb + (size_t)(n0 + r) * D + k0 + ci * 8);
        }
        cp_commit();
    };

    float rmv[4];
    float rsv[4];
#pragma unroll
    for (int u = 0; u < 4; u++) { rmv[u] = -1e30f; rsv[u] = 0.0f; }

    float acc[64];
#pragma unroll
    for (int q = 0; q < 64; q++) acc[q] = 0.0f;

    load_slab(0);
    load_slab(1);

    for (int t = 0; t < SLABS; t++) {
        if (t < SLABS - 1) cp_wait<1>(); else cp_wait<0>();
        __syncthreads();
        if (t + 2 < SLABS) load_slab(t + 2);

        uint32_t Ab = a_base + (t % NSTAGE) * A_STAGE;
        uint32_t Bb = b_base + (t % NSTAGE) * B_STAGE;
#pragma unroll
        for (int kk = 0; kk < 4; kk++) {
            uint32_t afr0[4];
            uint32_t afr1[4];
            uint32_t bfr[4][4];
            {
                int r = warpm * 32 + (lane & 15);
                uint32_t off = ((uint32_t)r * 128u + (uint32_t)kk * 32u
                               + (uint32_t)(lane >> 4) * 16u)
                             ^ ((uint32_t)(r & 7) << 4);
                ldmatrix_x4(afr0, Ab + off);
            }
            {
                int r = warpm * 32 + 16 + (lane & 15);
                uint32_t off = ((uint32_t)r * 128u + (uint32_t)kk * 32u
                               + (uint32_t)(lane >> 4) * 16u)
                             ^ ((uint32_t)(r & 7) << 4);
                ldmatrix_x4(afr1, Ab + off);
            }
#pragma unroll
            for (int g = 0; g < 4; g++) {
                int r = warpn * 64 + g * 16 + (lane & 15);
                uint32_t off = ((uint32_t)r * 128u + (uint32_t)kk * 32u
                               + (uint32_t)(lane >> 4) * 16u)
                             ^ ((uint32_t)(r & 7) << 4);
                ldmatrix_x4(bfr[g], Bb + off);
            }
#pragma unroll
            for (int g = 0; g < 4; g++) {
                mma16816(&acc[(2 * g + 0) * 4], afr0, bfr[g][0], bfr[g][2]);
                mma16816(&acc[(2 * g + 1) * 4], afr0, bfr[g][1], bfr[g][3]);
                mma16816(&acc[(8 + 2 * g + 0) * 4], afr1, bfr[g][0], bfr[g][2]);
                mma16816(&acc[(8 + 2 * g + 1) * 4], afr1, bfr[g][1], bfr[g][3]);
            }
        }

        if ((t & 7) == 7) {
            // epilogue: online LSE over this 128-col chunk
#pragma unroll
            for (int u = 0; u < 4; u++) {
                int mi = u >> 1;
                int h = u & 1;
                float vals[16];
#pragma unroll
                for (int j = 0; j < 8; j++) {
                    vals[2 * j + 0] = acc[(mi * 8 + j) * 4 + h * 2 + 0] * INV_T;
                    vals[2 * j + 1] = acc[(mi * 8 + j) * 4 + h * 2 + 1] * INV_T;
                }
                float vmax = vals[0];
#pragma unroll
                for (int q = 1; q < 16; q++) vmax = fmaxf(vmax, vals[q]);
                float vsum = 0.0f;
#pragma unroll
                for (int q = 0; q < 16; q++) vsum += __expf(vals[q] - vmax);
#pragma unroll
                for (int o = 1; o < 4; o <<= 1) {
                    float mo = __shfl_xor_sync(0xffffffffu, vmax, o);
                    float so = __shfl_xor_sync(0xffffffffu, vsum, o);
                    float nm = fmaxf(vmax, mo);
                    vsum = vsum * __expf(vmax - nm) + so * __expf(mo - nm);
                    vmax = nm;
                }
                if ((lane & 3) == 0) {
                    int lr = warpm * 32 + mi * 16 + h * 8 + (lane >> 2);
                    pm_s[warpn][lr] = vmax;
                    ps_s[warpn][lr] = vsum;
                }
            }
            __syncthreads();
            if (warpn == 0) {
#pragma unroll
                for (int u = 0; u < 4; u++) {
                    int mi = u >> 1;
                    int h = u & 1;
                    int lr = warpm * 32 + mi * 16 + h * 8 + (lane >> 2);
                    float m = pm_s[0][lr];
                    float s = ps_s[0][lr];
                    float mo = pm_s[1][lr];
                    float so = ps_s[1][lr];
                    float nm = fmaxf(m, mo);
                    s = s * __expf(m - nm) + so * __expf(mo - nm);
                    m = nm;
                    float nr = fmaxf(rmv[u], m);
                    rsv[u] = rsv[u] * __expf(rmv[u] - nr) + s * __expf(m - nr);
                    rmv[u] = nr;
                }
            }
            __syncthreads();
#pragma unroll
            for (int q = 0; q < 64; q++) acc[q] = 0.0f;
        }
    }

    if (warpn == 0 && (lane & 3) == 0) {
#pragma unroll
        for (int u = 0; u < 4; u++) {
            int mi = u >> 1;
            int h = u & 1;
            int row = m0 + warpm * 32 + mi * 16 + h * 8 + (lane >> 2);
            if (row < nPos) {
                g_pm[blockIdx.y * P_MAX + row] = rmv[u];
                g_ps[blockIdx.y * P_MAX + row] = rsv[u];
            }
        }
    }
}

// ---------------------------------------------------------------------------
// Finalize stage 1: 64 blocks x 128 thr. Blocks 0-31: pos rows (LSE combine +
// rowloss + per-block sums). Blocks 32-63: neg partial sums. Deterministic.
__global__ void k_fin1(int nPos, int nNeg) {
    int b = blockIdx.x;
    int t = threadIdx.x;
    __shared__ float r0[128];
    __shared__ float r1[128];
    if (b < 32) {
        int p = b * 128 + t;
        float lv = 0.0f;
        float pv = 0.0f;
        if (p < nPos) {
            float m = -1e30f;
            float s = 0.0f;
#pragma unroll
            for (int k = 0; k < NPART; k++) {
                float mk = g_pm[k * P_MAX + p];
                float sk = g_ps[k * P_MAX + p];
                float nm = fmaxf(m, mk);
                s = s * __expf(m - nm) + sk * __expf(mk - nm);
                m = nm;
            }
            float d = g_posdot[p];
            lv = m + logf(s) - d * INV_T;
            pv = d;
        }
        r0[t] = lv;
        r1[t] = pv;
        __syncthreads();
        for (int o = 64; o; o >>= 1) {
            if (t < o) { r0[t] += r0[t + o]; r1[t] += r1[t + o]; }
            __syncthreads();
        }
        if (t == 0) { g_part_l[b] = r0[0]; g_part_p[b] = r1[0]; }
    } else {
        int nb = b - 32;
        float nv = 0.0f;
#pragma unroll
        for (int i = 0; i < 4; i++) {
            int idx = nb * 512 + i * 128 + t;
            if (idx < nNeg) nv += g_negdot[idx];
        }
        r0[t] = nv;
        __syncthreads();
        for (int o = 64; o; o >>= 1) {
            if (t < o) r0[t] += r0[t + o];
            __syncthreads();
        }
        if (t == 0) g_part_n[nb] = r0[0];
    }
}

// Finalize stage 2: one warp sums 32 partials each. Deterministic.
__global__ void k_fin2(float* __restrict__ outp, int nPos, int nNeg, int out_size) {
    int t = threadIdx.x;
    float lv = (t < 32) ? g_part_l[t] : 0.0f;
    float pv = (t < 32) ? g_part_p[t] : 0.0f;
    float nv = (t < 32) ? g_part_n[t] : 0.0f;
#pragma unroll
    for (int o = 16; o; o >>= 1) {
        lv += __shfl_xor_sync(0xffffffffu, lv, o);
        pv += __shfl_xor_sync(0xffffffffu, pv, o);
        nv += __shfl_xor_sync(0xffffffffu, nv, o);
    }
    if (t == 0) {
        if (out_size > 0) outp[0] = lv / (float)nPos;
        if (out_size > 1) outp[1] = pv / (float)nPos;
        if (out_size > 2) outp[2] = nv / (float)nNeg;
    }
}

// ---------------------------------------------------------------------------
extern "C" void kernel_launch(void* const* d_in, const int* in_sizes, int n_in,
                              void* d_out, int out_size) {
    const float* emb = (const float*)d_in[0];
    const int* pa = (const int*)d_in[1];
    const int* pt = (const int*)d_in[2];
    const int* na = (const int*)d_in[3];
    const int* nt = (const int*)d_in[4];
    int nPos = in_sizes[1];
    int nNeg = in_sizes[3];

    cudaFuncSetAttribute(k_lse, cudaFuncAttributeMaxDynamicSharedMemorySize, SMEM_DYN);

    k_normalize<<<N_EMB, 128>>>(emb);

    int pairs = nPos + nNeg;
    int pblocks = (pairs * 32 + 255) / 256;
    k_pairdot<<<pblocks, 256>>>(pa, pt, na, nt, nPos, nNeg);

    dim3 grid((nPos + BM - 1) / BM, NSPLIT);
    k_lse<<<grid, 256, SMEM_DYN>>>(pa, nPos);

    k_fin1<<<64, 128>>>(nPos, nNeg);
    k_fin2<<<1, 32>>>((float*)d_out, nPos, nNeg, out_size);
}